// round 1
// baseline (speedup 1.0000x reference)
#include <cuda_runtime.h>

// Problem constants
constexpr int Bb  = 2;
constexpr int Ss  = 2048;
constexpr int Dd  = 1024;
constexpr int Hh  = 16;
constexpr int DKk = 64;
constexpr int Mm  = Bb * Ss;      // 4096 rows for projection GEMMs

// Scratch (device globals: allocation-free rule)
__device__ __align__(256) float g_Q [Bb * Hh * Ss * DKk];  // (B,H,S,DK)
__device__ __align__(256) float g_K [Bb * Hh * Ss * DKk];
__device__ __align__(256) float g_V [Bb * Hh * Ss * DKk];
__device__ __align__(256) float g_AO[Bb * Ss * Dd];        // (B,S,D) merged heads

// ---------------------------------------------------------------------------
// SGEMM: C[M,N] = X[M,K] @ W[N,K]^T + bias[N]
// 128x128 block tile, BK=16, 256 threads, 8x8 per thread (2x2 of 4x4).
// As/Bs stored transposed [k][m] for conflict-free float4 frag loads.
// MODE 0: out[m*N+n]
// MODE 1: head-split out[((b*H+h)*S+s)*DK+dk]  (m=b*S+s, n=h*DK+dk)
// ---------------------------------------------------------------------------
constexpr int GBM = 128, GBN = 128, GBK = 16;
constexpr int GP  = 132;   // smem pitch (floats)

template <int MODE>
__global__ __launch_bounds__(256, 2)
void gemm_kernel(const float* __restrict__ X, const float* __restrict__ W,
                 const float* __restrict__ bias, float* __restrict__ out,
                 int M, int N, int K)
{
    __shared__ float As[GBK][GP];
    __shared__ float Bs[GBK][GP];

    const int tid = threadIdx.x;
    const int tx = tid & 15;
    const int ty = tid >> 4;
    const int m0 = blockIdx.y * GBM;
    const int n0 = blockIdx.x * GBN;

    float acc[2][2][4][4];
    #pragma unroll
    for (int a = 0; a < 2; a++)
        #pragma unroll
        for (int b = 0; b < 2; b++)
            #pragma unroll
            for (int i = 0; i < 4; i++)
                #pragma unroll
                for (int j = 0; j < 4; j++)
                    acc[a][b][i][j] = 0.f;

    for (int k0 = 0; k0 < K; k0 += GBK) {
        // Stage tiles (transposed into smem)
        #pragma unroll
        for (int it = 0; it < 2; it++) {
            int c   = tid + it * 256;       // 0..511
            int row = c >> 2;               // 0..127
            int kc  = c & 3;                // 0..3 (float4 chunk along k)
            float4 va = *reinterpret_cast<const float4*>(
                &X[(size_t)(m0 + row) * K + k0 + kc * 4]);
            As[kc * 4 + 0][row] = va.x;
            As[kc * 4 + 1][row] = va.y;
            As[kc * 4 + 2][row] = va.z;
            As[kc * 4 + 3][row] = va.w;
            float4 vb = *reinterpret_cast<const float4*>(
                &W[(size_t)(n0 + row) * K + k0 + kc * 4]);
            Bs[kc * 4 + 0][row] = vb.x;
            Bs[kc * 4 + 1][row] = vb.y;
            Bs[kc * 4 + 2][row] = vb.z;
            Bs[kc * 4 + 3][row] = vb.w;
        }
        __syncthreads();

        #pragma unroll
        for (int kk = 0; kk < GBK; kk++) {
            float a[2][4], b[2][4];
            *reinterpret_cast<float4*>(a[0]) =
                *reinterpret_cast<const float4*>(&As[kk][ty * 4]);
            *reinterpret_cast<float4*>(a[1]) =
                *reinterpret_cast<const float4*>(&As[kk][64 + ty * 4]);
            *reinterpret_cast<float4*>(b[0]) =
                *reinterpret_cast<const float4*>(&Bs[kk][tx * 4]);
            *reinterpret_cast<float4*>(b[1]) =
                *reinterpret_cast<const float4*>(&Bs[kk][64 + tx * 4]);
            #pragma unroll
            for (int ib = 0; ib < 2; ib++)
                #pragma unroll
                for (int i = 0; i < 4; i++)
                    #pragma unroll
                    for (int jb = 0; jb < 2; jb++)
                        #pragma unroll
                        for (int j = 0; j < 4; j++)
                            acc[ib][jb][i][j] += a[ib][i] * b[jb][j];
        }
        __syncthreads();
    }

    // Epilogue
    #pragma unroll
    for (int ib = 0; ib < 2; ib++) {
        #pragma unroll
        for (int i = 0; i < 4; i++) {
            int m = m0 + ib * 64 + ty * 4 + i;
            #pragma unroll
            for (int jb = 0; jb < 2; jb++) {
                int n = n0 + jb * 64 + tx * 4;
                float4 bv = *reinterpret_cast<const float4*>(&bias[n]);
                float4 r;
                r.x = acc[ib][jb][i][0] + bv.x;
                r.y = acc[ib][jb][i][1] + bv.y;
                r.z = acc[ib][jb][i][2] + bv.z;
                r.w = acc[ib][jb][i][3] + bv.w;
                if (MODE == 0) {
                    *reinterpret_cast<float4*>(&out[(size_t)m * N + n]) = r;
                } else {
                    int bat = m / Ss, s = m % Ss;
                    int h   = n / DKk, dk = n % DKk;
                    *reinterpret_cast<float4*>(
                        &out[(((size_t)(bat * Hh + h)) * Ss + s) * DKk + dk]) = r;
                }
            }
        }
    }
}

// ---------------------------------------------------------------------------
// Flash attention (causal), fp32. One block per (q-tile, b*h).
// BQ = BK = 64, DK = 64. 256 threads = 16x16 grid, 4x4 microtile.
// Qs/Ks stored transposed [d][row] (conflict-free float4 frag loads),
// Vs stored [k][d], Ps stored [q][k].
// ---------------------------------------------------------------------------
constexpr int FPQ = 68;   // pitch for Qs/Ks/Vs (float4-aligned, conflict-free)
constexpr int FPP = 65;   // pitch for Ps
constexpr int FLASH_SMEM = (3 * 64 * FPQ + 64 * FPP) * 4;  // 68,864 B

__global__ __launch_bounds__(256)
void flash_kernel(const float* __restrict__ Q, const float* __restrict__ Kg_,
                  const float* __restrict__ Vg_, float* __restrict__ AO)
{
    extern __shared__ float sm[];
    float* Qs = sm;                  // [64][FPQ]  ([d][q])
    float* Ks = Qs + 64 * FPQ;       // [64][FPQ]  ([d][k])
    float* Vs = Ks + 64 * FPQ;       // [64][FPQ]  ([k][d])
    float* Ps = Vs + 64 * FPQ;       // [64][FPP]  ([q][k])

    const int tid = threadIdx.x;
    const int tx = tid & 15;
    const int ty = tid >> 4;
    const int qt = blockIdx.x;
    const int bh = blockIdx.y;
    const int qbase = qt * 64;
    const float scale = 0.125f;      // 1/sqrt(64)
    const float NEG = -1e30f;

    // Load Q tile (transposed)
    const float* Qgp = Q + ((size_t)bh * Ss + qbase) * DKk;
    #pragma unroll
    for (int it = 0; it < 4; it++) {
        int c  = tid + it * 256;     // 0..1023
        int r  = c >> 4;             // row 0..63
        int dc = c & 15;             // float4 chunk along d
        float4 v = *reinterpret_cast<const float4*>(&Qgp[(size_t)r * DKk + dc * 4]);
        Qs[(dc * 4 + 0) * FPQ + r] = v.x;
        Qs[(dc * 4 + 1) * FPQ + r] = v.y;
        Qs[(dc * 4 + 2) * FPQ + r] = v.z;
        Qs[(dc * 4 + 3) * FPQ + r] = v.w;
    }

    float m_i[4], l_i[4], oacc[4][4];
    #pragma unroll
    for (int i = 0; i < 4; i++) {
        m_i[i] = NEG;
        l_i[i] = 0.f;
        #pragma unroll
        for (int j = 0; j < 4; j++) oacc[i][j] = 0.f;
    }

    for (int kt = 0; kt <= qt; kt++) {
        const int kbase = kt * 64;
        const float* Kp = Kg_ + ((size_t)bh * Ss + kbase) * DKk;
        const float* Vp = Vg_ + ((size_t)bh * Ss + kbase) * DKk;

        __syncthreads();  // prior tile's GEMM2 done (and Qs staged on kt==0)
        #pragma unroll
        for (int it = 0; it < 4; it++) {
            int c  = tid + it * 256;
            int r  = c >> 4;
            int dc = c & 15;
            float4 vk = *reinterpret_cast<const float4*>(&Kp[(size_t)r * DKk + dc * 4]);
            Ks[(dc * 4 + 0) * FPQ + r] = vk.x;
            Ks[(dc * 4 + 1) * FPQ + r] = vk.y;
            Ks[(dc * 4 + 2) * FPQ + r] = vk.z;
            Ks[(dc * 4 + 3) * FPQ + r] = vk.w;
            float4 vv = *reinterpret_cast<const float4*>(&Vp[(size_t)r * DKk + dc * 4]);
            *reinterpret_cast<float4*>(&Vs[r * FPQ + dc * 4]) = vv;
        }
        __syncthreads();

        // GEMM1: S = Q @ K^T (64x64x64)
        float sfrag[4][4];
        #pragma unroll
        for (int i = 0; i < 4; i++)
            #pragma unroll
            for (int j = 0; j < 4; j++) sfrag[i][j] = 0.f;

        #pragma unroll 16
        for (int kk = 0; kk < DKk; kk++) {
            float4 a = *reinterpret_cast<const float4*>(&Qs[kk * FPQ + ty * 4]);
            float4 b = *reinterpret_cast<const float4*>(&Ks[kk * FPQ + tx * 4]);
            float av[4] = {a.x, a.y, a.z, a.w};
            float bv[4] = {b.x, b.y, b.z, b.w};
            #pragma unroll
            for (int i = 0; i < 4; i++)
                #pragma unroll
                for (int j = 0; j < 4; j++)
                    sfrag[i][j] += av[i] * bv[j];
        }

        // Scale + causal mask (only the diagonal tile needs masking)
        const bool diag = (kt == qt);
        #pragma unroll
        for (int i = 0; i < 4; i++) {
            int qg = qbase + ty * 4 + i;
            #pragma unroll
            for (int j = 0; j < 4; j++) {
                float s = sfrag[i][j] * scale;
                if (diag && (kbase + tx * 4 + j) > qg) s = NEG;
                sfrag[i][j] = s;
            }
        }

        // Online softmax per row (reduce across the 16-lane tx group)
        #pragma unroll
        for (int i = 0; i < 4; i++) {
            float r = fmaxf(fmaxf(sfrag[i][0], sfrag[i][1]),
                            fmaxf(sfrag[i][2], sfrag[i][3]));
            r = fmaxf(r, __shfl_xor_sync(0xffffffffu, r, 1));
            r = fmaxf(r, __shfl_xor_sync(0xffffffffu, r, 2));
            r = fmaxf(r, __shfl_xor_sync(0xffffffffu, r, 4));
            r = fmaxf(r, __shfl_xor_sync(0xffffffffu, r, 8));
            float mnew = fmaxf(m_i[i], r);
            float corr = __expf(m_i[i] - mnew);
            float rsum = 0.f;
            #pragma unroll
            for (int j = 0; j < 4; j++) {
                float p = __expf(sfrag[i][j] - mnew);
                sfrag[i][j] = p;
                rsum += p;
            }
            rsum += __shfl_xor_sync(0xffffffffu, rsum, 1);
            rsum += __shfl_xor_sync(0xffffffffu, rsum, 2);
            rsum += __shfl_xor_sync(0xffffffffu, rsum, 4);
            rsum += __shfl_xor_sync(0xffffffffu, rsum, 8);
            l_i[i] = l_i[i] * corr + rsum;
            m_i[i] = mnew;
            #pragma unroll
            for (int j = 0; j < 4; j++) {
                oacc[i][j] *= corr;
                Ps[(ty * 4 + i) * FPP + tx * 4 + j] = sfrag[i][j];
            }
        }
        __syncwarp();  // Ps rows are produced & consumed within the same warp

        // GEMM2: O += P @ V (64x64x64)
        #pragma unroll 16
        for (int kk = 0; kk < 64; kk++) {
            float4 b = *reinterpret_cast<const float4*>(&Vs[kk * FPQ + tx * 4]);
            float bv[4] = {b.x, b.y, b.z, b.w};
            #pragma unroll
            for (int i = 0; i < 4; i++) {
                float p = Ps[(ty * 4 + i) * FPP + kk];
                #pragma unroll
                for (int j = 0; j < 4; j++)
                    oacc[i][j] += p * bv[j];
            }
        }
    }

    // Epilogue: normalize + write merged-head layout (B,S,D)
    const int bat = bh / Hh, h = bh % Hh;
    #pragma unroll
    for (int i = 0; i < 4; i++) {
        int qg = qbase + ty * 4 + i;
        float inv = 1.0f / l_i[i];
        float4 r;
        r.x = oacc[i][0] * inv;
        r.y = oacc[i][1] * inv;
        r.z = oacc[i][2] * inv;
        r.w = oacc[i][3] * inv;
        *reinterpret_cast<float4*>(
            &AO[((size_t)bat * Ss + qg) * Dd + h * DKk + tx * 4]) = r;
    }
}

// ---------------------------------------------------------------------------
// Launch
// ---------------------------------------------------------------------------
extern "C" void kernel_launch(void* const* d_in, const int* in_sizes, int n_in,
                              void* d_out, int out_size)
{
    const float* query = (const float*)d_in[0];
    const float* key   = (const float*)d_in[1];
    const float* value = (const float*)d_in[2];
    // d_in[3] = mask (int32) — deterministically causal, handled analytically
    const float* Wq = (const float*)d_in[4];
    const float* bq = (const float*)d_in[5];
    const float* Wk = (const float*)d_in[6];
    const float* bk = (const float*)d_in[7];
    const float* Wv = (const float*)d_in[8];
    const float* bv = (const float*)d_in[9];
    const float* Wo = (const float*)d_in[10];
    const float* bo = (const float*)d_in[11];
    float* out = (float*)d_out;

    float *pQ, *pK, *pV, *pAO;
    cudaGetSymbolAddress((void**)&pQ,  g_Q);
    cudaGetSymbolAddress((void**)&pK,  g_K);
    cudaGetSymbolAddress((void**)&pV,  g_V);
    cudaGetSymbolAddress((void**)&pAO, g_AO);

    dim3 ggrid(Dd / GBN, Mm / GBM);   // (8, 32)
    gemm_kernel<1><<<ggrid, 256>>>(query, Wq, bq, pQ, Mm, Dd, Dd);
    gemm_kernel<1><<<ggrid, 256>>>(key,   Wk, bk, pK, Mm, Dd, Dd);
    gemm_kernel<1><<<ggrid, 256>>>(value, Wv, bv, pV, Mm, Dd, Dd);

    cudaFuncSetAttribute(flash_kernel,
                         cudaFuncAttributeMaxDynamicSharedMemorySize, FLASH_SMEM);
    dim3 fgrid(Ss / 64, Bb * Hh);     // (32, 32)
    flash_kernel<<<fgrid, 256, FLASH_SMEM>>>(pQ, pK, pV, pAO);

    gemm_kernel<0><<<ggrid, 256>>>(pAO, Wo, bo, out, Mm, Dd, Dd);
}

// round 3
// speedup vs baseline: 2.5903x; 2.5903x over previous
#include <cuda_runtime.h>
#include <cstdint>

// Problem constants
constexpr int Bb  = 2;
constexpr int Ss  = 2048;
constexpr int Dd  = 1024;
constexpr int Hh  = 16;
constexpr int DKk = 64;
constexpr int Mm  = Bb * Ss;

// Scratch (device globals: allocation-free rule)
__device__ __align__(256) float g_Q [Bb * Hh * Ss * DKk];
__device__ __align__(256) float g_K [Bb * Hh * Ss * DKk];
__device__ __align__(256) float g_V [Bb * Hh * Ss * DKk];
__device__ __align__(256) float g_AO[Bb * Ss * Dd];

// ---------------------------------------------------------------------------
// Helpers
// ---------------------------------------------------------------------------
__device__ __forceinline__ uint32_t smem_u32(const void* p) {
    uint32_t a;
    asm("{ .reg .u64 t; cvta.to.shared.u64 t, %1; cvt.u32.u64 %0, t; }"
        : "=r"(a) : "l"(p));
    return a;
}
__device__ __forceinline__ uint32_t f2tf32(float f) {
    uint32_t r;
    asm("cvt.rna.tf32.f32 %0, %1;" : "=r"(r) : "f"(f));
    return r;
}
__device__ __forceinline__ void sts128(uint32_t a, uint32_t x, uint32_t y,
                                       uint32_t z, uint32_t w) {
    asm volatile("st.shared.v4.b32 [%0], {%1,%2,%3,%4};"
                 :: "r"(a), "r"(x), "r"(y), "r"(z), "r"(w) : "memory");
}
#define LDSM_X4(r0, r1, r2, r3, addr)                                          \
    asm volatile("ldmatrix.sync.aligned.m8n8.x4.shared.b16 {%0,%1,%2,%3}, [%4];" \
                 : "=r"(r0), "=r"(r1), "=r"(r2), "=r"(r3) : "r"(addr))

#define MMA_TF32(c, a, b)                                                      \
    asm volatile("mma.sync.aligned.m16n8k8.row.col.f32.tf32.tf32.f32 "         \
                 "{%0,%1,%2,%3}, {%4,%5,%6,%7}, {%8,%9}, {%0,%1,%2,%3};"       \
                 : "+f"((c)[0]), "+f"((c)[1]), "+f"((c)[2]), "+f"((c)[3])      \
                 : "r"((a)[0]), "r"((a)[1]), "r"((a)[2]), "r"((a)[3]),         \
                   "r"((b)[0]), "r"((b)[1]))

// ---------------------------------------------------------------------------
// TF32 mma.sync GEMM: C[M,N] = X[M,K] @ W[N,K]^T + bias
// CTA 128x128, BK=32, double-buffered smem, 8 warps (2M x 4N), warp 64x32.
// Smem tiles [row][k]: 128 rows x 128B, 16B-chunk swizzle c ^= (row & 7).
// MODE 0: flat out[m*N+n]; MODE 1: head-split (B,H,S,DK)
// ---------------------------------------------------------------------------
constexpr int TBM = 128, TBN = 128, TBK = 32;
constexpr int TILE_BYTES  = TBM * TBK * 4;          // 16 KB
constexpr int STAGE_BYTES = 2 * TILE_BYTES;         // A + B
constexpr int GEMM_SMEM   = 2 * STAGE_BYTES;        // 64 KB (2 stages)

template <int MODE>
__global__ __launch_bounds__(256)
void gemm_mma(const float* __restrict__ X, const float* __restrict__ W,
              const float* __restrict__ bias, float* __restrict__ out,
              int M, int N, int K)
{
    extern __shared__ char smem[];
    const uint32_t sb = smem_u32(smem);
    const int tid  = threadIdx.x;
    const int wid  = tid >> 5;
    const int lane = tid & 31;
    const int m0 = blockIdx.y * TBM;
    const int n0 = blockIdx.x * TBN;
    const int wm = (wid & 1) * 64;       // warp M offset
    const int wn = (wid >> 1) * 32;      // warp N offset

    // ldmatrix per-lane row decode
    const int g4 = lane >> 3;            // matrix id within x4
    const int i8 = lane & 7;             // row within matrix
    const int rA  = wm + ((g4 & 1) << 3) + i8;       // + mt*16
    const int cAb = g4 >> 1;                          // k-chunk bit
    const int rB  = wn + ((g4 >> 1) << 3) + i8;      // + pair*16
    const int cBb = g4 & 1;

    float c[4][4][4];
    #pragma unroll
    for (int mt = 0; mt < 4; mt++)
        #pragma unroll
        for (int nt = 0; nt < 4; nt++)
            #pragma unroll
            for (int r = 0; r < 4; r++) c[mt][nt][r] = 0.f;

    const int NKB = K / TBK;

    // Staging decode (each thread: 4 float4 chunks per tile)
    // idx = tid + i*256 -> row = idx>>3 (0..127), chunk = idx&7
    // Prologue: stage kb=0 into buffer 0
    {
        const float* Ag = X + (size_t)m0 * K;
        const float* Bg = W + (size_t)n0 * K;
        #pragma unroll
        for (int i = 0; i < 4; i++) {
            const int idx = tid + i * 256;
            const int row = idx >> 3, ch = idx & 7;
            const uint32_t off = (uint32_t)(row * 128 + ((ch ^ (row & 7)) << 4));
            float4 va = *reinterpret_cast<const float4*>(Ag + (size_t)row * K + ch * 4);
            sts128(sb + off, f2tf32(va.x), f2tf32(va.y), f2tf32(va.z), f2tf32(va.w));
            float4 vb = *reinterpret_cast<const float4*>(Bg + (size_t)row * K + ch * 4);
            sts128(sb + TILE_BYTES + off,
                   f2tf32(vb.x), f2tf32(vb.y), f2tf32(vb.z), f2tf32(vb.w));
        }
    }
    __syncthreads();

    for (int kb = 0; kb < NKB; kb++) {
        // Prefetch next tile into registers
        float4 ra[4], rb[4];
        if (kb + 1 < NKB) {
            const float* Ag = X + (size_t)m0 * K + (kb + 1) * TBK;
            const float* Bg = W + (size_t)n0 * K + (kb + 1) * TBK;
            #pragma unroll
            for (int i = 0; i < 4; i++) {
                const int idx = tid + i * 256;
                const int row = idx >> 3, ch = idx & 7;
                ra[i] = *reinterpret_cast<const float4*>(Ag + (size_t)row * K + ch * 4);
                rb[i] = *reinterpret_cast<const float4*>(Bg + (size_t)row * K + ch * 4);
            }
        }

        // Compute on current buffer
        const uint32_t Ab = sb + (kb & 1) * STAGE_BYTES;
        const uint32_t Bm = Ab + TILE_BYTES;
        #pragma unroll
        for (int ks = 0; ks < 4; ks++) {
            uint32_t a[4][4], b[4][2];
            #pragma unroll
            for (int mt = 0; mt < 4; mt++) {
                const int row = rA + mt * 16;
                const uint32_t ad = Ab + row * 128 +
                    ((((2 * ks + cAb) ^ (rA & 7)) & 7) << 4);
                LDSM_X4(a[mt][0], a[mt][1], a[mt][2], a[mt][3], ad);
            }
            #pragma unroll
            for (int p = 0; p < 2; p++) {
                const int row = rB + p * 16;
                const uint32_t bd = Bm + row * 128 +
                    ((((2 * ks + cBb) ^ (rB & 7)) & 7) << 4);
                LDSM_X4(b[p * 2][0], b[p * 2][1], b[p * 2 + 1][0], b[p * 2 + 1][1], bd);
            }
            #pragma unroll
            for (int mt = 0; mt < 4; mt++)
                #pragma unroll
                for (int nt = 0; nt < 4; nt++)
                    MMA_TF32(c[mt][nt], a[mt], b[nt]);
        }

        // Store prefetched tile into the other buffer
        if (kb + 1 < NKB) {
            const uint32_t An = sb + ((kb + 1) & 1) * STAGE_BYTES;
            const uint32_t Bn = An + TILE_BYTES;
            #pragma unroll
            for (int i = 0; i < 4; i++) {
                const int idx = tid + i * 256;
                const int row = idx >> 3, ch = idx & 7;
                const uint32_t off = (uint32_t)(row * 128 + ((ch ^ (row & 7)) << 4));
                sts128(An + off, f2tf32(ra[i].x), f2tf32(ra[i].y),
                                 f2tf32(ra[i].z), f2tf32(ra[i].w));
                sts128(Bn + off, f2tf32(rb[i].x), f2tf32(rb[i].y),
                                 f2tf32(rb[i].z), f2tf32(rb[i].w));
            }
        }
        __syncthreads();
    }

    // Epilogue: c0->(g,2t) c1->(g,2t+1) c2->(g+8,2t) c3->(g+8,2t+1)
    const int g  = lane >> 2;
    const int t2 = (lane & 3) * 2;
    #pragma unroll
    for (int mt = 0; mt < 4; mt++) {
        #pragma unroll
        for (int nt = 0; nt < 4; nt++) {
            const int n = n0 + wn + nt * 8 + t2;
            const float2 bv = *reinterpret_cast<const float2*>(bias + n);
            #pragma unroll
            for (int half = 0; half < 2; half++) {
                const int m = m0 + wm + mt * 16 + g + half * 8;
                float2 o;
                o.x = c[mt][nt][half * 2 + 0] + bv.x;
                o.y = c[mt][nt][half * 2 + 1] + bv.y;
                if (MODE == 0) {
                    *reinterpret_cast<float2*>(&out[(size_t)m * N + n]) = o;
                } else {
                    const int bat = m >> 11, s = m & 2047;
                    const int h = n >> 6, dk = n & 63;
                    *reinterpret_cast<float2*>(
                        &out[(((size_t)(bat * Hh + h)) * Ss + s) * DKk + dk]) = o;
                }
            }
        }
    }
}

// ---------------------------------------------------------------------------
// Flash attention (causal), fp32 — unchanged (round-1 proven); tensorize next
// ---------------------------------------------------------------------------
constexpr int FPQ = 68;
constexpr int FPP = 65;
constexpr int FLASH_SMEM = (3 * 64 * FPQ + 64 * FPP) * 4;

__global__ __launch_bounds__(256)
void flash_kernel(const float* __restrict__ Q, const float* __restrict__ Kg_,
                  const float* __restrict__ Vg_, float* __restrict__ AO)
{
    extern __shared__ float sm[];
    float* Qs = sm;
    float* Ks = Qs + 64 * FPQ;
    float* Vs = Ks + 64 * FPQ;
    float* Ps = Vs + 64 * FPQ;

    const int tid = threadIdx.x;
    const int tx = tid & 15;
    const int ty = tid >> 4;
    const int qt = blockIdx.x;
    const int bh = blockIdx.y;
    const int qbase = qt * 64;
    const float scale = 0.125f;
    const float NEG = -1e30f;

    const float* Qgp = Q + ((size_t)bh * Ss + qbase) * DKk;
    #pragma unroll
    for (int it = 0; it < 4; it++) {
        int c  = tid + it * 256;
        int r  = c >> 4;
        int dc = c & 15;
        float4 v = *reinterpret_cast<const float4*>(&Qgp[(size_t)r * DKk + dc * 4]);
        Qs[(dc * 4 + 0) * FPQ + r] = v.x;
        Qs[(dc * 4 + 1) * FPQ + r] = v.y;
        Qs[(dc * 4 + 2) * FPQ + r] = v.z;
        Qs[(dc * 4 + 3) * FPQ + r] = v.w;
    }

    float m_i[4], l_i[4], oacc[4][4];
    #pragma unroll
    for (int i = 0; i < 4; i++) {
        m_i[i] = NEG;
        l_i[i] = 0.f;
        #pragma unroll
        for (int j = 0; j < 4; j++) oacc[i][j] = 0.f;
    }

    for (int kt = 0; kt <= qt; kt++) {
        const int kbase = kt * 64;
        const float* Kp = Kg_ + ((size_t)bh * Ss + kbase) * DKk;
        const float* Vp = Vg_ + ((size_t)bh * Ss + kbase) * DKk;

        __syncthreads();
        #pragma unroll
        for (int it = 0; it < 4; it++) {
            int c  = tid + it * 256;
            int r  = c >> 4;
            int dc = c & 15;
            float4 vk = *reinterpret_cast<const float4*>(&Kp[(size_t)r * DKk + dc * 4]);
            Ks[(dc * 4 + 0) * FPQ + r] = vk.x;
            Ks[(dc * 4 + 1) * FPQ + r] = vk.y;
            Ks[(dc * 4 + 2) * FPQ + r] = vk.z;
            Ks[(dc * 4 + 3) * FPQ + r] = vk.w;
            float4 vv = *reinterpret_cast<const float4*>(&Vp[(size_t)r * DKk + dc * 4]);
            *reinterpret_cast<float4*>(&Vs[r * FPQ + dc * 4]) = vv;
        }
        __syncthreads();

        float sfrag[4][4];
        #pragma unroll
        for (int i = 0; i < 4; i++)
            #pragma unroll
            for (int j = 0; j < 4; j++) sfrag[i][j] = 0.f;

        #pragma unroll 16
        for (int kk = 0; kk < DKk; kk++) {
            float4 a = *reinterpret_cast<const float4*>(&Qs[kk * FPQ + ty * 4]);
            float4 b = *reinterpret_cast<const float4*>(&Ks[kk * FPQ + tx * 4]);
            float av[4] = {a.x, a.y, a.z, a.w};
            float bv[4] = {b.x, b.y, b.z, b.w};
            #pragma unroll
            for (int i = 0; i < 4; i++)
                #pragma unroll
                for (int j = 0; j < 4; j++)
                    sfrag[i][j] += av[i] * bv[j];
        }

        const bool diag = (kt == qt);
        #pragma unroll
        for (int i = 0; i < 4; i++) {
            int qg = qbase + ty * 4 + i;
            #pragma unroll
            for (int j = 0; j < 4; j++) {
                float s = sfrag[i][j] * scale;
                if (diag && (kbase + tx * 4 + j) > qg) s = NEG;
                sfrag[i][j] = s;
            }
        }

        #pragma unroll
        for (int i = 0; i < 4; i++) {
            float r = fmaxf(fmaxf(sfrag[i][0], sfrag[i][1]),
                            fmaxf(sfrag[i][2], sfrag[i][3]));
            r = fmaxf(r, __shfl_xor_sync(0xffffffffu, r, 1));
            r = fmaxf(r, __shfl_xor_sync(0xffffffffu, r, 2));
            r = fmaxf(r, __shfl_xor_sync(0xffffffffu, r, 4));
            r = fmaxf(r, __shfl_xor_sync(0xffffffffu, r, 8));
            float mnew = fmaxf(m_i[i], r);
            float corr = __expf(m_i[i] - mnew);
            float rsum = 0.f;
            #pragma unroll
            for (int j = 0; j < 4; j++) {
                float p = __expf(sfrag[i][j] - mnew);
                sfrag[i][j] = p;
                rsum += p;
            }
            rsum += __shfl_xor_sync(0xffffffffu, rsum, 1);
            rsum += __shfl_xor_sync(0xffffffffu, rsum, 2);
            rsum += __shfl_xor_sync(0xffffffffu, rsum, 4);
            rsum += __shfl_xor_sync(0xffffffffu, rsum, 8);
            l_i[i] = l_i[i] * corr + rsum;
            m_i[i] = mnew;
            #pragma unroll
            for (int j = 0; j < 4; j++) {
                oacc[i][j] *= corr;
                Ps[(ty * 4 + i) * FPP + tx * 4 + j] = sfrag[i][j];
            }
        }
        __syncwarp();

        #pragma unroll 16
        for (int kk = 0; kk < 64; kk++) {
            float4 b = *reinterpret_cast<const float4*>(&Vs[kk * FPQ + tx * 4]);
            float bv[4] = {b.x, b.y, b.z, b.w};
            #pragma unroll
            for (int i = 0; i < 4; i++) {
                float p = Ps[(ty * 4 + i) * FPP + kk];
                #pragma unroll
                for (int j = 0; j < 4; j++)
                    oacc[i][j] += p * bv[j];
            }
        }
    }

    const int bat = bh / Hh, h = bh % Hh;
    #pragma unroll
    for (int i = 0; i < 4; i++) {
        int qg = qbase + ty * 4 + i;
        float inv = 1.0f / l_i[i];
        float4 r;
        r.x = oacc[i][0] * inv;
        r.y = oacc[i][1] * inv;
        r.z = oacc[i][2] * inv;
        r.w = oacc[i][3] * inv;
        *reinterpret_cast<float4*>(
            &AO[((size_t)bat * Ss + qg) * Dd + h * DKk + tx * 4]) = r;
    }
}

// ---------------------------------------------------------------------------
// Launch
// ---------------------------------------------------------------------------
extern "C" void kernel_launch(void* const* d_in, const int* in_sizes, int n_in,
                              void* d_out, int out_size)
{
    const float* query = (const float*)d_in[0];
    const float* key   = (const float*)d_in[1];
    const float* value = (const float*)d_in[2];
    // d_in[3] = mask (causal, handled analytically)
    const float* Wq = (const float*)d_in[4];
    const float* bq = (const float*)d_in[5];
    const float* Wk = (const float*)d_in[6];
    const float* bk = (const float*)d_in[7];
    const float* Wv = (const float*)d_in[8];
    const float* bv = (const float*)d_in[9];
    const float* Wo = (const float*)d_in[10];
    const float* bo = (const float*)d_in[11];
    float* out = (float*)d_out;

    float *pQ, *pK, *pV, *pAO;
    cudaGetSymbolAddress((void**)&pQ,  g_Q);
    cudaGetSymbolAddress((void**)&pK,  g_K);
    cudaGetSymbolAddress((void**)&pV,  g_V);
    cudaGetSymbolAddress((void**)&pAO, g_AO);

    static bool attr_set = false;
    if (!attr_set) {
        cudaFuncSetAttribute(gemm_mma<0>, cudaFuncAttributeMaxDynamicSharedMemorySize, GEMM_SMEM);
        cudaFuncSetAttribute(gemm_mma<1>, cudaFuncAttributeMaxDynamicSharedMemorySize, GEMM_SMEM);
        cudaFuncSetAttribute(flash_kernel, cudaFuncAttributeMaxDynamicSharedMemorySize, FLASH_SMEM);
        attr_set = true;
    }

    dim3 ggrid(Dd / TBN, Mm / TBM);   // (8, 32)
    gemm_mma<1><<<ggrid, 256, GEMM_SMEM>>>(query, Wq, bq, pQ, Mm, Dd, Dd);
    gemm_mma<1><<<ggrid, 256, GEMM_SMEM>>>(key,   Wk, bk, pK, Mm, Dd, Dd);
    gemm_mma<1><<<ggrid, 256, GEMM_SMEM>>>(value, Wv, bv, pV, Mm, Dd, Dd);

    dim3 fgrid(Ss / 64, Bb * Hh);     // (32, 32)
    flash_kernel<<<fgrid, 256, FLASH_SMEM>>>(pQ, pK, pV, pAO);

    gemm_mma<0><<<ggrid, 256, GEMM_SMEM>>>(pAO, Wo, bo, out, Mm, Dd, Dd);
}

// round 4
// speedup vs baseline: 4.5448x; 1.7546x over previous
#include <cuda_runtime.h>
#include <cstdint>

// Problem constants
constexpr int Bb  = 2;
constexpr int Ss  = 2048;
constexpr int Dd  = 1024;
constexpr int Hh  = 16;
constexpr int DKk = 64;
constexpr int Mm  = Bb * Ss;

// Scratch (device globals: allocation-free rule)
__device__ __align__(256) float g_Q [Bb * Hh * Ss * DKk];
__device__ __align__(256) float g_K [Bb * Hh * Ss * DKk];
__device__ __align__(256) float g_V [Bb * Hh * Ss * DKk];
__device__ __align__(256) float g_AO[Bb * Ss * Dd];

// ---------------------------------------------------------------------------
// Helpers
// ---------------------------------------------------------------------------
__device__ __forceinline__ uint32_t smem_u32(const void* p) {
    uint32_t a;
    asm("{ .reg .u64 t; cvta.to.shared.u64 t, %1; cvt.u32.u64 %0, t; }"
        : "=r"(a) : "l"(p));
    return a;
}
__device__ __forceinline__ uint32_t f2tf32(float f) {
    uint32_t r;
    asm("cvt.rna.tf32.f32 %0, %1;" : "=r"(r) : "f"(f));
    return r;
}
__device__ __forceinline__ void sts128(uint32_t a, uint32_t x, uint32_t y,
                                       uint32_t z, uint32_t w) {
    asm volatile("st.shared.v4.b32 [%0], {%1,%2,%3,%4};"
                 :: "r"(a), "r"(x), "r"(y), "r"(z), "r"(w) : "memory");
}
__device__ __forceinline__ void sts64(uint32_t a, uint32_t x, uint32_t y) {
    asm volatile("st.shared.v2.b32 [%0], {%1,%2};"
                 :: "r"(a), "r"(x), "r"(y) : "memory");
}
__device__ __forceinline__ void sts32(uint32_t a, uint32_t x) {
    asm volatile("st.shared.b32 [%0], %1;" :: "r"(a), "r"(x) : "memory");
}
#define LDSM_X4(r0, r1, r2, r3, addr)                                          \
    asm volatile("ldmatrix.sync.aligned.m8n8.x4.shared.b16 {%0,%1,%2,%3}, [%4];" \
                 : "=r"(r0), "=r"(r1), "=r"(r2), "=r"(r3) : "r"(addr))

#define MMA_TF32(c, a, b)                                                      \
    asm volatile("mma.sync.aligned.m16n8k8.row.col.f32.tf32.tf32.f32 "         \
                 "{%0,%1,%2,%3}, {%4,%5,%6,%7}, {%8,%9}, {%0,%1,%2,%3};"       \
                 : "+f"((c)[0]), "+f"((c)[1]), "+f"((c)[2]), "+f"((c)[3])      \
                 : "r"((a)[0]), "r"((a)[1]), "r"((a)[2]), "r"((a)[3]),         \
                   "r"((b)[0]), "r"((b)[1]))

// ---------------------------------------------------------------------------
// TF32 mma.sync GEMM (verified round 3): C[M,N] = X[M,K] @ W[N,K]^T + bias
// ---------------------------------------------------------------------------
constexpr int TBM = 128, TBN = 128, TBK = 32;
constexpr int TILE_BYTES  = TBM * TBK * 4;
constexpr int STAGE_BYTES = 2 * TILE_BYTES;
constexpr int GEMM_SMEM   = 2 * STAGE_BYTES;

template <int MODE>
__global__ __launch_bounds__(256)
void gemm_mma(const float* __restrict__ X, const float* __restrict__ W,
              const float* __restrict__ bias, float* __restrict__ out,
              int M, int N, int K)
{
    extern __shared__ char smem[];
    const uint32_t sb = smem_u32(smem);
    const int tid  = threadIdx.x;
    const int wid  = tid >> 5;
    const int lane = tid & 31;
    const int m0 = blockIdx.y * TBM;
    const int n0 = blockIdx.x * TBN;
    const int wm = (wid & 1) * 64;
    const int wn = (wid >> 1) * 32;

    const int g4 = lane >> 3;
    const int i8 = lane & 7;
    const int rA  = wm + ((g4 & 1) << 3) + i8;
    const int cAb = g4 >> 1;
    const int rB  = wn + ((g4 >> 1) << 3) + i8;
    const int cBb = g4 & 1;

    float c[4][4][4];
    #pragma unroll
    for (int mt = 0; mt < 4; mt++)
        #pragma unroll
        for (int nt = 0; nt < 4; nt++)
            #pragma unroll
            for (int r = 0; r < 4; r++) c[mt][nt][r] = 0.f;

    const int NKB = K / TBK;

    {
        const float* Ag = X + (size_t)m0 * K;
        const float* Bg = W + (size_t)n0 * K;
        #pragma unroll
        for (int i = 0; i < 4; i++) {
            const int idx = tid + i * 256;
            const int row = idx >> 3, ch = idx & 7;
            const uint32_t off = (uint32_t)(row * 128 + ((ch ^ (row & 7)) << 4));
            float4 va = *reinterpret_cast<const float4*>(Ag + (size_t)row * K + ch * 4);
            sts128(sb + off, f2tf32(va.x), f2tf32(va.y), f2tf32(va.z), f2tf32(va.w));
            float4 vb = *reinterpret_cast<const float4*>(Bg + (size_t)row * K + ch * 4);
            sts128(sb + TILE_BYTES + off,
                   f2tf32(vb.x), f2tf32(vb.y), f2tf32(vb.z), f2tf32(vb.w));
        }
    }
    __syncthreads();

    for (int kb = 0; kb < NKB; kb++) {
        float4 ra[4], rb[4];
        if (kb + 1 < NKB) {
            const float* Ag = X + (size_t)m0 * K + (kb + 1) * TBK;
            const float* Bg = W + (size_t)n0 * K + (kb + 1) * TBK;
            #pragma unroll
            for (int i = 0; i < 4; i++) {
                const int idx = tid + i * 256;
                const int row = idx >> 3, ch = idx & 7;
                ra[i] = *reinterpret_cast<const float4*>(Ag + (size_t)row * K + ch * 4);
                rb[i] = *reinterpret_cast<const float4*>(Bg + (size_t)row * K + ch * 4);
            }
        }

        const uint32_t Ab = sb + (kb & 1) * STAGE_BYTES;
        const uint32_t Bm = Ab + TILE_BYTES;
        #pragma unroll
        for (int ks = 0; ks < 4; ks++) {
            uint32_t a[4][4], b[4][2];
            #pragma unroll
            for (int mt = 0; mt < 4; mt++) {
                const int row = rA + mt * 16;
                const uint32_t ad = Ab + row * 128 +
                    ((((2 * ks + cAb) ^ (rA & 7)) & 7) << 4);
                LDSM_X4(a[mt][0], a[mt][1], a[mt][2], a[mt][3], ad);
            }
            #pragma unroll
            for (int p = 0; p < 2; p++) {
                const int row = rB + p * 16;
                const uint32_t bd = Bm + row * 128 +
                    ((((2 * ks + cBb) ^ (rB & 7)) & 7) << 4);
                LDSM_X4(b[p * 2][0], b[p * 2][1], b[p * 2 + 1][0], b[p * 2 + 1][1], bd);
            }
            #pragma unroll
            for (int mt = 0; mt < 4; mt++)
                #pragma unroll
                for (int nt = 0; nt < 4; nt++)
                    MMA_TF32(c[mt][nt], a[mt], b[nt]);
        }

        if (kb + 1 < NKB) {
            const uint32_t An = sb + ((kb + 1) & 1) * STAGE_BYTES;
            const uint32_t Bn = An + TILE_BYTES;
            #pragma unroll
            for (int i = 0; i < 4; i++) {
                const int idx = tid + i * 256;
                const int row = idx >> 3, ch = idx & 7;
                const uint32_t off = (uint32_t)(row * 128 + ((ch ^ (row & 7)) << 4));
                sts128(An + off, f2tf32(ra[i].x), f2tf32(ra[i].y),
                                 f2tf32(ra[i].z), f2tf32(ra[i].w));
                sts128(Bn + off, f2tf32(rb[i].x), f2tf32(rb[i].y),
                                 f2tf32(rb[i].z), f2tf32(rb[i].w));
            }
        }
        __syncthreads();
    }

    const int g  = lane >> 2;
    const int t2 = (lane & 3) * 2;
    #pragma unroll
    for (int mt = 0; mt < 4; mt++) {
        #pragma unroll
        for (int nt = 0; nt < 4; nt++) {
            const int n = n0 + wn + nt * 8 + t2;
            const float2 bv = *reinterpret_cast<const float2*>(bias + n);
            #pragma unroll
            for (int half = 0; half < 2; half++) {
                const int m = m0 + wm + mt * 16 + g + half * 8;
                float2 o;
                o.x = c[mt][nt][half * 2 + 0] + bv.x;
                o.y = c[mt][nt][half * 2 + 1] + bv.y;
                if (MODE == 0) {
                    *reinterpret_cast<float2*>(&out[(size_t)m * N + n]) = o;
                } else {
                    const int bat = m >> 11, s = m & 2047;
                    const int h = n >> 6, dk = n & 63;
                    *reinterpret_cast<float2*>(
                        &out[(((size_t)(bat * Hh + h)) * Ss + s) * DKk + dk]) = o;
                }
            }
        }
    }
}

// ---------------------------------------------------------------------------
// Tensor-core flash attention (causal), TF32 mma.sync.
// CTA: 128 q-rows, KV tiles of 64. 8 warps, each warp 16 q-rows x 64 cols.
// Qs/Ks/Vt/Ps tf32 in smem, pitch 256B, chunk swizzle ch ^= (row&7).
// Vt = V transposed [dk][k]. Softmax in registers (quad shfl).
// ---------------------------------------------------------------------------
constexpr int FSM = (128 * 64 + 64 * 64 + 64 * 64 + 128 * 64) * 4;  // 96 KB

__global__ __launch_bounds__(256, 2)
void flash_tc(const float* __restrict__ Qg, const float* __restrict__ Kg,
              const float* __restrict__ Vg, float* __restrict__ AO)
{
    extern __shared__ char smem[];
    const uint32_t sb = smem_u32(smem);
    const uint32_t Qs = sb;
    const uint32_t Ks = sb + 128 * 256;
    const uint32_t Vt = Ks + 64 * 256;
    const uint32_t Ps = Vt + 64 * 256;

    const int tid  = threadIdx.x;
    const int wid  = tid >> 5;
    const int lane = tid & 31;
    const int g4 = lane >> 3, i8 = lane & 7;
    const int g  = lane >> 2, t  = lane & 3;
    const int qt = (int)gridDim.x - 1 - (int)blockIdx.x;  // heavy CTAs first
    const int bh = blockIdx.y;
    const int qbase = qt * 128;
    const float scale = 0.125f;

    // Stage Q tile once (128 x 64 tf32, swizzled)
    const float* Qp = Qg + ((size_t)bh * Ss + qbase) * DKk;
    #pragma unroll
    for (int i = 0; i < 8; i++) {
        const int idx = tid + i * 256;
        const int row = idx >> 4, ch = idx & 15;
        float4 v = *reinterpret_cast<const float4*>(Qp + (size_t)row * DKk + ch * 4);
        sts128(Qs + row * 256 + ((ch ^ (row & 7)) << 4),
               f2tf32(v.x), f2tf32(v.y), f2tf32(v.z), f2tf32(v.w));
    }

    float o[8][4];
    #pragma unroll
    for (int nt = 0; nt < 8; nt++)
        #pragma unroll
        for (int e = 0; e < 4; e++) o[nt][e] = 0.f;
    float m0 = -1e30f, m1 = -1e30f, l0 = 0.f, l1 = 0.f;

    const int arow  = wid * 16 + ((g4 & 1) << 3) + i8;   // A frag row (Qs/Ps)
    const int browb = ((g4 >> 1) << 3) + i8;             // B frag row base
    const int cA = g4 >> 1;                              // A chunk low bit
    const int cB = g4 & 1;                               // B chunk low bit
    const int qg0 = qbase + wid * 16 + g;                // global q rows
    const int qg1 = qg0 + 8;
    const int prow0 = wid * 16 + g;                      // Ps rows

    const int jmax = 2 * qt + 1;
    for (int j = 0; j <= jmax; j++) {
        const int kbase = j * 64;
        const float* Kp = Kg + ((size_t)bh * Ss + kbase) * DKk;
        const float* Vp = Vg + ((size_t)bh * Ss + kbase) * DKk;

        __syncthreads();   // Ks/Vt consumed by all warps in prev iter
        // Stage K (row-major) and V (transposed) as tf32
        #pragma unroll
        for (int i = 0; i < 4; i++) {
            const int idx = tid + i * 256;
            {   // K: row = idx>>4 (0..63), chunk = idx&15
                const int row = idx >> 4, ch = idx & 15;
                float4 v = *reinterpret_cast<const float4*>(
                    Kp + (size_t)row * DKk + ch * 4);
                sts128(Ks + row * 256 + ((ch ^ (row & 7)) << 4),
                       f2tf32(v.x), f2tf32(v.y), f2tf32(v.z), f2tf32(v.w));
            }
            {   // V transpose: row = idx&63 (k), chunk = idx>>6 (dk chunk)
                const int row = idx & 63, ch = idx >> 6;
                float4 v = *reinterpret_cast<const float4*>(
                    Vp + (size_t)row * DKk + ch * 4);
                const float vv[4] = {v.x, v.y, v.z, v.w};
                #pragma unroll
                for (int e = 0; e < 4; e++) {
                    const int dr = ch * 4 + e;   // Vt row = dk index
                    sts32(Vt + dr * 256 + (((row >> 2) ^ (dr & 7)) << 4)
                             + (row & 3) * 4,
                          f2tf32(vv[e]));
                }
            }
        }
        __syncthreads();

        // ---- S = Q @ K^T (warp: 16 x 64, K=64) ----
        float s[8][4];
        #pragma unroll
        for (int nt = 0; nt < 8; nt++)
            #pragma unroll
            for (int e = 0; e < 4; e++) s[nt][e] = 0.f;

        #pragma unroll
        for (int ks = 0; ks < 8; ks++) {
            uint32_t a[4], b[8][2];
            LDSM_X4(a[0], a[1], a[2], a[3],
                    Qs + arow * 256 + (((2 * ks + cA) ^ (arow & 7)) << 4));
            #pragma unroll
            for (int p = 0; p < 4; p++) {
                const int br = p * 16 + browb;
                LDSM_X4(b[2 * p][0], b[2 * p][1], b[2 * p + 1][0], b[2 * p + 1][1],
                        Ks + br * 256 + (((2 * ks + cB) ^ (br & 7)) << 4));
            }
            #pragma unroll
            for (int nt = 0; nt < 8; nt++) MMA_TF32(s[nt], a, b[nt]);
        }

        // ---- scale + causal mask + online softmax (registers) ----
        const bool msk = (j >= 2 * qt);
        float mx0 = -1e30f, mx1 = -1e30f;
        #pragma unroll
        for (int nt = 0; nt < 8; nt++) {
            const int c0 = kbase + nt * 8 + 2 * t;
            s[nt][0] *= scale; s[nt][1] *= scale;
            s[nt][2] *= scale; s[nt][3] *= scale;
            if (msk) {
                if (c0     > qg0) s[nt][0] = -1e30f;
                if (c0 + 1 > qg0) s[nt][1] = -1e30f;
                if (c0     > qg1) s[nt][2] = -1e30f;
                if (c0 + 1 > qg1) s[nt][3] = -1e30f;
            }
            mx0 = fmaxf(mx0, fmaxf(s[nt][0], s[nt][1]));
            mx1 = fmaxf(mx1, fmaxf(s[nt][2], s[nt][3]));
        }
        mx0 = fmaxf(mx0, __shfl_xor_sync(0xffffffffu, mx0, 1));
        mx0 = fmaxf(mx0, __shfl_xor_sync(0xffffffffu, mx0, 2));
        mx1 = fmaxf(mx1, __shfl_xor_sync(0xffffffffu, mx1, 1));
        mx1 = fmaxf(mx1, __shfl_xor_sync(0xffffffffu, mx1, 2));

        const float mn0 = fmaxf(m0, mx0), mn1 = fmaxf(m1, mx1);
        const float corr0 = __expf(m0 - mn0), corr1 = __expf(m1 - mn1);
        float rs0 = 0.f, rs1 = 0.f;
        #pragma unroll
        for (int nt = 0; nt < 8; nt++) {
            const float p00 = __expf(s[nt][0] - mn0);
            const float p01 = __expf(s[nt][1] - mn0);
            const float p10 = __expf(s[nt][2] - mn1);
            const float p11 = __expf(s[nt][3] - mn1);
            rs0 += p00 + p01;
            rs1 += p10 + p11;
            const int cch = 2 * nt + (t >> 1);
            const uint32_t boff = (uint32_t)(((2 * t) & 3) * 4);
            sts64(Ps + prow0 * 256 + ((cch ^ (prow0 & 7)) << 4) + boff,
                  f2tf32(p00), f2tf32(p01));
            sts64(Ps + (prow0 + 8) * 256 + ((cch ^ ((prow0 + 8) & 7)) << 4) + boff,
                  f2tf32(p10), f2tf32(p11));
            o[nt][0] *= corr0; o[nt][1] *= corr0;
            o[nt][2] *= corr1; o[nt][3] *= corr1;
        }
        rs0 += __shfl_xor_sync(0xffffffffu, rs0, 1);
        rs0 += __shfl_xor_sync(0xffffffffu, rs0, 2);
        rs1 += __shfl_xor_sync(0xffffffffu, rs1, 1);
        rs1 += __shfl_xor_sync(0xffffffffu, rs1, 2);
        l0 = l0 * corr0 + rs0;
        l1 = l1 * corr1 + rs1;
        m0 = mn0; m1 = mn1;
        __syncwarp();

        // ---- O += P @ V (warp: 16 x 64, K=64) ----
        #pragma unroll
        for (int ks = 0; ks < 8; ks++) {
            uint32_t a[4], b[8][2];
            LDSM_X4(a[0], a[1], a[2], a[3],
                    Ps + arow * 256 + (((2 * ks + cA) ^ (arow & 7)) << 4));
            #pragma unroll
            for (int p = 0; p < 4; p++) {
                const int br = p * 16 + browb;
                LDSM_X4(b[2 * p][0], b[2 * p][1], b[2 * p + 1][0], b[2 * p + 1][1],
                        Vt + br * 256 + (((2 * ks + cB) ^ (br & 7)) << 4));
            }
            #pragma unroll
            for (int nt = 0; nt < 8; nt++) MMA_TF32(o[nt], a, b[nt]);
        }
    }

    // Epilogue: normalize, write merged-head (B,S,D)
    const int bat = bh >> 4, h = bh & 15;
    const float inv0 = 1.f / l0, inv1 = 1.f / l1;
    #pragma unroll
    for (int nt = 0; nt < 8; nt++) {
        const int col = h * 64 + nt * 8 + 2 * t;
        float2 r0, r1;
        r0.x = o[nt][0] * inv0; r0.y = o[nt][1] * inv0;
        r1.x = o[nt][2] * inv1; r1.y = o[nt][3] * inv1;
        *reinterpret_cast<float2*>(&AO[((size_t)bat * Ss + qg0) * Dd + col]) = r0;
        *reinterpret_cast<float2*>(&AO[((size_t)bat * Ss + qg1) * Dd + col]) = r1;
    }
}

// ---------------------------------------------------------------------------
// Launch
// ---------------------------------------------------------------------------
extern "C" void kernel_launch(void* const* d_in, const int* in_sizes, int n_in,
                              void* d_out, int out_size)
{
    const float* query = (const float*)d_in[0];
    const float* key   = (const float*)d_in[1];
    const float* value = (const float*)d_in[2];
    // d_in[3] = mask (causal, handled analytically)
    const float* Wq = (const float*)d_in[4];
    const float* bq = (const float*)d_in[5];
    const float* Wk = (const float*)d_in[6];
    const float* bk = (const float*)d_in[7];
    const float* Wv = (const float*)d_in[8];
    const float* bv = (const float*)d_in[9];
    const float* Wo = (const float*)d_in[10];
    const float* bo = (const float*)d_in[11];
    float* out = (float*)d_out;

    float *pQ, *pK, *pV, *pAO;
    cudaGetSymbolAddress((void**)&pQ,  g_Q);
    cudaGetSymbolAddress((void**)&pK,  g_K);
    cudaGetSymbolAddress((void**)&pV,  g_V);
    cudaGetSymbolAddress((void**)&pAO, g_AO);

    static bool attr_set = false;
    if (!attr_set) {
        cudaFuncSetAttribute(gemm_mma<0>, cudaFuncAttributeMaxDynamicSharedMemorySize, GEMM_SMEM);
        cudaFuncSetAttribute(gemm_mma<1>, cudaFuncAttributeMaxDynamicSharedMemorySize, GEMM_SMEM);
        cudaFuncSetAttribute(flash_tc,    cudaFuncAttributeMaxDynamicSharedMemorySize, FSM);
        attr_set = true;
    }

    dim3 ggrid(Dd / TBN, Mm / TBM);   // (8, 32)
    gemm_mma<1><<<ggrid, 256, GEMM_SMEM>>>(query, Wq, bq, pQ, Mm, Dd, Dd);
    gemm_mma<1><<<ggrid, 256, GEMM_SMEM>>>(key,   Wk, bk, pK, Mm, Dd, Dd);
    gemm_mma<1><<<ggrid, 256, GEMM_SMEM>>>(value, Wv, bv, pV, Mm, Dd, Dd);

    dim3 fgrid(Ss / 128, Bb * Hh);    // (16, 32)
    flash_tc<<<fgrid, 256, FSM>>>(pQ, pK, pV, pAO);

    gemm_mma<0><<<ggrid, 256, GEMM_SMEM>>>(pAO, Wo, bo, out, Mm, Dd, Dd);
}

// round 5
// speedup vs baseline: 4.5824x; 1.0083x over previous
#include <cuda_runtime.h>
#include <cstdint>

// Problem constants
constexpr int Bb  = 2;
constexpr int Ss  = 2048;
constexpr int Dd  = 1024;
constexpr int Hh  = 16;
constexpr int DKk = 64;
constexpr int Mm  = Bb * Ss;

// Scratch (device globals: allocation-free rule)
__device__ __align__(256) float g_Q [Bb * Hh * Ss * DKk];
__device__ __align__(256) float g_K [Bb * Hh * Ss * DKk];
__device__ __align__(256) float g_V [Bb * Hh * Ss * DKk];
__device__ __align__(256) float g_AO[Bb * Ss * Dd];

// ---------------------------------------------------------------------------
// Helpers
// ---------------------------------------------------------------------------
__device__ __forceinline__ uint32_t smem_u32(const void* p) {
    uint32_t a;
    asm("{ .reg .u64 t; cvta.to.shared.u64 t, %1; cvt.u32.u64 %0, t; }"
        : "=r"(a) : "l"(p));
    return a;
}
__device__ __forceinline__ uint32_t f2tf32(float f) {
    uint32_t r;
    asm("cvt.rna.tf32.f32 %0, %1;" : "=r"(r) : "f"(f));
    return r;
}
__device__ __forceinline__ void sts128(uint32_t a, uint32_t x, uint32_t y,
                                       uint32_t z, uint32_t w) {
    asm volatile("st.shared.v4.b32 [%0], {%1,%2,%3,%4};"
                 :: "r"(a), "r"(x), "r"(y), "r"(z), "r"(w) : "memory");
}
__device__ __forceinline__ void sts32(uint32_t a, uint32_t x) {
    asm volatile("st.shared.b32 [%0], %1;" :: "r"(a), "r"(x) : "memory");
}
#define LDSM_X4(r0, r1, r2, r3, addr)                                          \
    asm volatile("ldmatrix.sync.aligned.m8n8.x4.shared.b16 {%0,%1,%2,%3}, [%4];" \
                 : "=r"(r0), "=r"(r1), "=r"(r2), "=r"(r3) : "r"(addr))

#define MMA_TF32(c, a, b)                                                      \
    asm volatile("mma.sync.aligned.m16n8k8.row.col.f32.tf32.tf32.f32 "         \
                 "{%0,%1,%2,%3}, {%4,%5,%6,%7}, {%8,%9}, {%0,%1,%2,%3};"       \
                 : "+f"((c)[0]), "+f"((c)[1]), "+f"((c)[2]), "+f"((c)[3])      \
                 : "r"((a)[0]), "r"((a)[1]), "r"((a)[2]), "r"((a)[3]),         \
                   "r"((b)[0]), "r"((b)[1]))

// ---------------------------------------------------------------------------
// TF32 mma.sync GEMM (verified round 3): C[M,N] = X[M,K] @ W[N,K]^T + bias
// ---------------------------------------------------------------------------
constexpr int TBM = 128, TBN = 128, TBK = 32;
constexpr int TILE_BYTES  = TBM * TBK * 4;
constexpr int STAGE_BYTES = 2 * TILE_BYTES;
constexpr int GEMM_SMEM   = 2 * STAGE_BYTES;

template <int MODE>
__global__ __launch_bounds__(256)
void gemm_mma(const float* __restrict__ X, const float* __restrict__ W,
              const float* __restrict__ bias, float* __restrict__ out,
              int M, int N, int K)
{
    extern __shared__ char smem[];
    const uint32_t sb = smem_u32(smem);
    const int tid  = threadIdx.x;
    const int wid  = tid >> 5;
    const int lane = tid & 31;
    const int m0 = blockIdx.y * TBM;
    const int n0 = blockIdx.x * TBN;
    const int wm = (wid & 1) * 64;
    const int wn = (wid >> 1) * 32;

    const int g4 = lane >> 3;
    const int i8 = lane & 7;
    const int rA  = wm + ((g4 & 1) << 3) + i8;
    const int cAb = g4 >> 1;
    const int rB  = wn + ((g4 >> 1) << 3) + i8;
    const int cBb = g4 & 1;

    float c[4][4][4];
    #pragma unroll
    for (int mt = 0; mt < 4; mt++)
        #pragma unroll
        for (int nt = 0; nt < 4; nt++)
            #pragma unroll
            for (int r = 0; r < 4; r++) c[mt][nt][r] = 0.f;

    const int NKB = K / TBK;

    {
        const float* Ag = X + (size_t)m0 * K;
        const float* Bg = W + (size_t)n0 * K;
        #pragma unroll
        for (int i = 0; i < 4; i++) {
            const int idx = tid + i * 256;
            const int row = idx >> 3, ch = idx & 7;
            const uint32_t off = (uint32_t)(row * 128 + ((ch ^ (row & 7)) << 4));
            float4 va = *reinterpret_cast<const float4*>(Ag + (size_t)row * K + ch * 4);
            sts128(sb + off, f2tf32(va.x), f2tf32(va.y), f2tf32(va.z), f2tf32(va.w));
            float4 vb = *reinterpret_cast<const float4*>(Bg + (size_t)row * K + ch * 4);
            sts128(sb + TILE_BYTES + off,
                   f2tf32(vb.x), f2tf32(vb.y), f2tf32(vb.z), f2tf32(vb.w));
        }
    }
    __syncthreads();

    for (int kb = 0; kb < NKB; kb++) {
        float4 ra[4], rb[4];
        if (kb + 1 < NKB) {
            const float* Ag = X + (size_t)m0 * K + (kb + 1) * TBK;
            const float* Bg = W + (size_t)n0 * K + (kb + 1) * TBK;
            #pragma unroll
            for (int i = 0; i < 4; i++) {
                const int idx = tid + i * 256;
                const int row = idx >> 3, ch = idx & 7;
                ra[i] = *reinterpret_cast<const float4*>(Ag + (size_t)row * K + ch * 4);
                rb[i] = *reinterpret_cast<const float4*>(Bg + (size_t)row * K + ch * 4);
            }
        }

        const uint32_t Ab = sb + (kb & 1) * STAGE_BYTES;
        const uint32_t Bm = Ab + TILE_BYTES;
        #pragma unroll
        for (int ks = 0; ks < 4; ks++) {
            uint32_t a[4][4], b[4][2];
            #pragma unroll
            for (int mt = 0; mt < 4; mt++) {
                const int row = rA + mt * 16;
                const uint32_t ad = Ab + row * 128 +
                    ((((2 * ks + cAb) ^ (rA & 7)) & 7) << 4);
                LDSM_X4(a[mt][0], a[mt][1], a[mt][2], a[mt][3], ad);
            }
            #pragma unroll
            for (int p = 0; p < 2; p++) {
                const int row = rB + p * 16;
                const uint32_t bd = Bm + row * 128 +
                    ((((2 * ks + cBb) ^ (rB & 7)) & 7) << 4);
                LDSM_X4(b[p * 2][0], b[p * 2][1], b[p * 2 + 1][0], b[p * 2 + 1][1], bd);
            }
            #pragma unroll
            for (int mt = 0; mt < 4; mt++)
                #pragma unroll
                for (int nt = 0; nt < 4; nt++)
                    MMA_TF32(c[mt][nt], a[mt], b[nt]);
        }

        if (kb + 1 < NKB) {
            const uint32_t An = sb + ((kb + 1) & 1) * STAGE_BYTES;
            const uint32_t Bn = An + TILE_BYTES;
            #pragma unroll
            for (int i = 0; i < 4; i++) {
                const int idx = tid + i * 256;
                const int row = idx >> 3, ch = idx & 7;
                const uint32_t off = (uint32_t)(row * 128 + ((ch ^ (row & 7)) << 4));
                sts128(An + off, f2tf32(ra[i].x), f2tf32(ra[i].y),
                                 f2tf32(ra[i].z), f2tf32(ra[i].w));
                sts128(Bn + off, f2tf32(rb[i].x), f2tf32(rb[i].y),
                                 f2tf32(rb[i].z), f2tf32(rb[i].w));
            }
        }
        __syncthreads();
    }

    const int g  = lane >> 2;
    const int t2 = (lane & 3) * 2;
    #pragma unroll
    for (int mt = 0; mt < 4; mt++) {
        #pragma unroll
        for (int nt = 0; nt < 4; nt++) {
            const int n = n0 + wn + nt * 8 + t2;
            const float2 bv = *reinterpret_cast<const float2*>(bias + n);
            #pragma unroll
            for (int half = 0; half < 2; half++) {
                const int m = m0 + wm + mt * 16 + g + half * 8;
                float2 o;
                o.x = c[mt][nt][half * 2 + 0] + bv.x;
                o.y = c[mt][nt][half * 2 + 1] + bv.y;
                if (MODE == 0) {
                    *reinterpret_cast<float2*>(&out[(size_t)m * N + n]) = o;
                } else {
                    const int bat = m >> 11, s = m & 2047;
                    const int h = n >> 6, dk = n & 63;
                    *reinterpret_cast<float2*>(
                        &out[(((size_t)(bat * Hh + h)) * Ss + s) * DKk + dk]) = o;
                }
            }
        }
    }
}

// ---------------------------------------------------------------------------
// Tensor-core flash attention v2 (causal), TF32 mma.sync.
// CTA: 128 q-rows, KV tiles of 64. 8 warps, each 16 q-rows x 64 cols.
// Double-buffered K/Vt (register-prefetch staging), ONE sync per tile.
// P kept in registers: PV A-fragments built by quad shuffles (no P smem).
// smem: Qs 32K + 2x Ks 16K + 2x Vt 16K = 96K.
// ---------------------------------------------------------------------------
constexpr int FQ_B   = 128 * 256;                 // 32 KB
constexpr int FK_B   = 64 * 256;                  // 16 KB
constexpr int FSM2   = FQ_B + 4 * FK_B;           // 96 KB

__global__ __launch_bounds__(256, 2)
void flash_tc(const float* __restrict__ Qg, const float* __restrict__ Kg,
              const float* __restrict__ Vg, float* __restrict__ AO)
{
    extern __shared__ char smem[];
    const uint32_t sb  = smem_u32(smem);
    const uint32_t Qs  = sb;
    const uint32_t Ksb[2] = { sb + FQ_B,          sb + FQ_B + FK_B };
    const uint32_t Vtb[2] = { sb + FQ_B + 2*FK_B, sb + FQ_B + 3*FK_B };

    const int tid  = threadIdx.x;
    const int wid  = tid >> 5;
    const int lane = tid & 31;
    const int g4 = lane >> 3, i8 = lane & 7;
    const int g  = lane >> 2, t  = lane & 3;
    const int qt = (int)gridDim.x - 1 - (int)blockIdx.x;  // heavy CTAs first
    const int bh = blockIdx.y;
    const int qbase = qt * 128;
    const float sl2 = 0.1803368801111137f;   // (1/8) * log2(e)
    const float NEG = -1e30f;

    // Staging decode (constant per thread)
    const int krow[4] = { (tid          ) >> 4, (tid + 256) >> 4,
                          (tid + 512    ) >> 4, (tid + 768) >> 4 };
    const int kch     = tid & 15;
    const int vrow    = tid & 63;           // k index
    const int vch0    = tid >> 6;           // dk chunk base (adds +4 per i)

    // Stage Q tile once (128 x 64 tf32, swizzled)
    const float* Qp = Qg + ((size_t)bh * Ss + qbase) * DKk;
    #pragma unroll
    for (int i = 0; i < 8; i++) {
        const int idx = tid + i * 256;
        const int row = idx >> 4, ch = idx & 15;
        float4 v = *reinterpret_cast<const float4*>(Qp + (size_t)row * DKk + ch * 4);
        sts128(Qs + row * 256 + ((ch ^ (row & 7)) << 4),
               f2tf32(v.x), f2tf32(v.y), f2tf32(v.z), f2tf32(v.w));
    }
    // Stage K/V tile j=0 into buffer 0
    {
        const float* Kp = Kg + (size_t)bh * Ss * DKk;
        const float* Vp = Vg + (size_t)bh * Ss * DKk;
        #pragma unroll
        for (int i = 0; i < 4; i++) {
            float4 vk = *reinterpret_cast<const float4*>(
                Kp + (size_t)krow[i] * DKk + kch * 4);
            sts128(Ksb[0] + krow[i] * 256 + ((kch ^ (krow[i] & 7)) << 4),
                   f2tf32(vk.x), f2tf32(vk.y), f2tf32(vk.z), f2tf32(vk.w));
            const int vch = vch0 + i * 4;
            float4 vv = *reinterpret_cast<const float4*>(
                Vp + (size_t)vrow * DKk + vch * 4);
            const float ve[4] = {vv.x, vv.y, vv.z, vv.w};
            #pragma unroll
            for (int e = 0; e < 4; e++) {
                const int dr = vch * 4 + e;
                sts32(Vtb[0] + dr * 256 + (((vrow >> 2) ^ (dr & 7)) << 4)
                              + (vrow & 3) * 4, f2tf32(ve[e]));
            }
        }
    }
    __syncthreads();

    float o[8][4];
    #pragma unroll
    for (int nt = 0; nt < 8; nt++)
        #pragma unroll
        for (int e = 0; e < 4; e++) o[nt][e] = 0.f;
    float m0 = NEG, m1 = NEG, l0 = 0.f, l1 = 0.f;

    const int arow  = wid * 16 + ((g4 & 1) << 3) + i8;
    const int browb = ((g4 >> 1) << 3) + i8;
    const int cA = g4 >> 1;
    const int cB = g4 & 1;
    const int qg0 = qbase + wid * 16 + g;
    const int qg1 = qg0 + 8;
    const int shA = (lane & 28) + (t >> 1);  // quad src for col t
    const bool odd = (t & 1);

    const int jmax = 2 * qt + 1;
    for (int j = 0; j <= jmax; j++) {
        const int kbase = j * 64;
        const bool nxt = (j < jmax);
        const uint32_t Kb = Ksb[j & 1], Vb = Vtb[j & 1];

        // Prefetch K[j+1]
        float4 kpre[4];
        if (nxt) {
            const float* Kp = Kg + ((size_t)bh * Ss + kbase + 64) * DKk;
            #pragma unroll
            for (int i = 0; i < 4; i++)
                kpre[i] = *reinterpret_cast<const float4*>(
                    Kp + (size_t)krow[i] * DKk + kch * 4);
        }

        // ---- S = Q @ K^T (warp: 16 x 64, K=64) ----
        float s[8][4];
        #pragma unroll
        for (int nt = 0; nt < 8; nt++)
            #pragma unroll
            for (int e = 0; e < 4; e++) s[nt][e] = 0.f;

        #pragma unroll
        for (int ks = 0; ks < 8; ks++) {
            uint32_t a[4], b[8][2];
            LDSM_X4(a[0], a[1], a[2], a[3],
                    Qs + arow * 256 + (((2 * ks + cA) ^ (arow & 7)) << 4));
            #pragma unroll
            for (int p = 0; p < 4; p++) {
                const int br = p * 16 + browb;
                LDSM_X4(b[2 * p][0], b[2 * p][1], b[2 * p + 1][0], b[2 * p + 1][1],
                        Kb + br * 256 + (((2 * ks + cB) ^ (br & 7)) << 4));
            }
            #pragma unroll
            for (int nt = 0; nt < 8; nt++) MMA_TF32(s[nt], a, b[nt]);
        }

        // Store prefetched K into the other buffer
        if (nxt) {
            const uint32_t Kn = Ksb[(j + 1) & 1];
            #pragma unroll
            for (int i = 0; i < 4; i++)
                sts128(Kn + krow[i] * 256 + ((kch ^ (krow[i] & 7)) << 4),
                       f2tf32(kpre[i].x), f2tf32(kpre[i].y),
                       f2tf32(kpre[i].z), f2tf32(kpre[i].w));
        }

        // Prefetch V[j+1]
        float4 vpre[4];
        if (nxt) {
            const float* Vp = Vg + ((size_t)bh * Ss + kbase + 64) * DKk;
            #pragma unroll
            for (int i = 0; i < 4; i++)
                vpre[i] = *reinterpret_cast<const float4*>(
                    Vp + (size_t)vrow * DKk + (vch0 + i * 4) * 4);
        }

        // ---- scale (log2 domain) + causal mask + online softmax ----
        const bool msk = (j >= 2 * qt);
        float mx0 = NEG, mx1 = NEG;
        #pragma unroll
        for (int nt = 0; nt < 8; nt++) {
            const int c0 = kbase + nt * 8 + 2 * t;
            s[nt][0] *= sl2; s[nt][1] *= sl2;
            s[nt][2] *= sl2; s[nt][3] *= sl2;
            if (msk) {
                if (c0     > qg0) s[nt][0] = NEG;
                if (c0 + 1 > qg0) s[nt][1] = NEG;
                if (c0     > qg1) s[nt][2] = NEG;
                if (c0 + 1 > qg1) s[nt][3] = NEG;
            }
            mx0 = fmaxf(mx0, fmaxf(s[nt][0], s[nt][1]));
            mx1 = fmaxf(mx1, fmaxf(s[nt][2], s[nt][3]));
        }
        mx0 = fmaxf(mx0, __shfl_xor_sync(0xffffffffu, mx0, 1));
        mx0 = fmaxf(mx0, __shfl_xor_sync(0xffffffffu, mx0, 2));
        mx1 = fmaxf(mx1, __shfl_xor_sync(0xffffffffu, mx1, 1));
        mx1 = fmaxf(mx1, __shfl_xor_sync(0xffffffffu, mx1, 2));

        const float mn0 = fmaxf(m0, mx0), mn1 = fmaxf(m1, mx1);
        const float corr0 = exp2f(m0 - mn0), corr1 = exp2f(m1 - mn1);
        float rs0 = 0.f, rs1 = 0.f;
        #pragma unroll
        for (int nt = 0; nt < 8; nt++) {
            s[nt][0] = exp2f(s[nt][0] - mn0);
            s[nt][1] = exp2f(s[nt][1] - mn0);
            s[nt][2] = exp2f(s[nt][2] - mn1);
            s[nt][3] = exp2f(s[nt][3] - mn1);
            rs0 += s[nt][0] + s[nt][1];
            rs1 += s[nt][2] + s[nt][3];
            o[nt][0] *= corr0; o[nt][1] *= corr0;
            o[nt][2] *= corr1; o[nt][3] *= corr1;
        }
        rs0 += __shfl_xor_sync(0xffffffffu, rs0, 1);
        rs0 += __shfl_xor_sync(0xffffffffu, rs0, 2);
        rs1 += __shfl_xor_sync(0xffffffffu, rs1, 1);
        rs1 += __shfl_xor_sync(0xffffffffu, rs1, 2);
        l0 = l0 * corr0 + rs0;
        l1 = l1 * corr1 + rs1;
        m0 = mn0; m1 = mn1;

        // ---- O += P @ V : A-frags from registers via quad shuffles ----
        #pragma unroll
        for (int ks = 0; ks < 8; ks++) {
            // A-frag (cols 8ks + {t, t+4}, rows g, g+8)
            const float v00 = __shfl_sync(0xffffffffu, s[ks][0], shA);
            const float v01 = __shfl_sync(0xffffffffu, s[ks][1], shA);
            const float v10 = __shfl_sync(0xffffffffu, s[ks][2], shA);
            const float v11 = __shfl_sync(0xffffffffu, s[ks][3], shA);
            const float v02 = __shfl_sync(0xffffffffu, s[ks][0], shA + 2);
            const float v03 = __shfl_sync(0xffffffffu, s[ks][1], shA + 2);
            const float v12 = __shfl_sync(0xffffffffu, s[ks][2], shA + 2);
            const float v13 = __shfl_sync(0xffffffffu, s[ks][3], shA + 2);
            uint32_t a[4];
            a[0] = f2tf32(odd ? v01 : v00);
            a[1] = f2tf32(odd ? v11 : v10);
            a[2] = f2tf32(odd ? v03 : v02);
            a[3] = f2tf32(odd ? v13 : v12);

            uint32_t b[8][2];
            #pragma unroll
            for (int p = 0; p < 4; p++) {
                const int br = p * 16 + browb;
                LDSM_X4(b[2 * p][0], b[2 * p][1], b[2 * p + 1][0], b[2 * p + 1][1],
                        Vb + br * 256 + (((2 * ks + cB) ^ (br & 7)) << 4));
            }
            #pragma unroll
            for (int nt = 0; nt < 8; nt++) MMA_TF32(o[nt], a, b[nt]);
        }

        // Store prefetched V (transposed) into the other buffer
        if (nxt) {
            const uint32_t Vn = Vtb[(j + 1) & 1];
            #pragma unroll
            for (int i = 0; i < 4; i++) {
                const int vch = vch0 + i * 4;
                const float ve[4] = {vpre[i].x, vpre[i].y, vpre[i].z, vpre[i].w};
                #pragma unroll
                for (int e = 0; e < 4; e++) {
                    const int dr = vch * 4 + e;
                    sts32(Vn + dr * 256 + (((vrow >> 2) ^ (dr & 7)) << 4)
                             + (vrow & 3) * 4, f2tf32(ve[e]));
                }
            }
        }
        __syncthreads();
    }

    // Epilogue: normalize, write merged-head (B,S,D)
    const int bat = bh >> 4, h = bh & 15;
    const float inv0 = 1.f / l0, inv1 = 1.f / l1;
    #pragma unroll
    for (int nt = 0; nt < 8; nt++) {
        const int col = h * 64 + nt * 8 + 2 * t;
        float2 r0, r1;
        r0.x = o[nt][0] * inv0; r0.y = o[nt][1] * inv0;
        r1.x = o[nt][2] * inv1; r1.y = o[nt][3] * inv1;
        *reinterpret_cast<float2*>(&AO[((size_t)bat * Ss + qg0) * Dd + col]) = r0;
        *reinterpret_cast<float2*>(&AO[((size_t)bat * Ss + qg1) * Dd + col]) = r1;
    }
}

// ---------------------------------------------------------------------------
// Launch
// ---------------------------------------------------------------------------
extern "C" void kernel_launch(void* const* d_in, const int* in_sizes, int n_in,
                              void* d_out, int out_size)
{
    const float* query = (const float*)d_in[0];
    const float* key   = (const float*)d_in[1];
    const float* value = (const float*)d_in[2];
    // d_in[3] = mask (causal, handled analytically)
    const float* Wq = (const float*)d_in[4];
    const float* bq = (const float*)d_in[5];
    const float* Wk = (const float*)d_in[6];
    const float* bk = (const float*)d_in[7];
    const float* Wv = (const float*)d_in[8];
    const float* bv = (const float*)d_in[9];
    const float* Wo = (const float*)d_in[10];
    const float* bo = (const float*)d_in[11];
    float* out = (float*)d_out;

    float *pQ, *pK, *pV, *pAO;
    cudaGetSymbolAddress((void**)&pQ,  g_Q);
    cudaGetSymbolAddress((void**)&pK,  g_K);
    cudaGetSymbolAddress((void**)&pV,  g_V);
    cudaGetSymbolAddress((void**)&pAO, g_AO);

    static bool attr_set = false;
    if (!attr_set) {
        cudaFuncSetAttribute(gemm_mma<0>, cudaFuncAttributeMaxDynamicSharedMemorySize, GEMM_SMEM);
        cudaFuncSetAttribute(gemm_mma<1>, cudaFuncAttributeMaxDynamicSharedMemorySize, GEMM_SMEM);
        cudaFuncSetAttribute(flash_tc,    cudaFuncAttributeMaxDynamicSharedMemorySize, FSM2);
        attr_set = true;
    }

    dim3 ggrid(Dd / TBN, Mm / TBM);   // (8, 32)
    gemm_mma<1><<<ggrid, 256, GEMM_SMEM>>>(query, Wq, bq, pQ, Mm, Dd, Dd);
    gemm_mma<1><<<ggrid, 256, GEMM_SMEM>>>(key,   Wk, bk, pK, Mm, Dd, Dd);
    gemm_mma<1><<<ggrid, 256, GEMM_SMEM>>>(value, Wv, bv, pV, Mm, Dd, Dd);

    dim3 fgrid(Ss / 128, Bb * Hh);    // (16, 32)
    flash_tc<<<fgrid, 256, FSM2>>>(pQ, pK, pV, pAO);

    gemm_mma<0><<<ggrid, 256, GEMM_SMEM>>>(pAO, Wo, bo, out, Mm, Dd, Dd);
}